// round 11
// baseline (speedup 1.0000x reference)
#include <cuda_runtime.h>
#include <cuda_fp16.h>
#include <cstdint>

#define KVOL 27
#define MAXN 131072
#define TILE_M 128
#define ROWB 80     // smem bytes per 32-half row (64B data + 16B pad)
#define STAGES 5
#define A_STAGE_B (16 * ROWB)                    // 1280 B per warp-stage
#define A_REGION  (8 * STAGES * A_STAGE_B)       // 51200 B
#define IDX_OFF   A_REGION                       // idx block after A region
#define DSMEM_B   (A_REGION + KVOL * TILE_M * 4) // 65024 B

// ---------------------------------------------------------------------------
// Scratch (device globals — allocation rules forbid cudaMalloc)
// ---------------------------------------------------------------------------
__device__ static int      g_nbr[KVOL * MAXN];               // nbr[k][o] = in idx or -1
__device__ __align__(16) static __half   g_fh[MAXN * 32];    // feats, fp16
__device__ __align__(16) static uint32_t g_wfh[KVOL * 512];  // lane-order fp16 B frags
__device__ static float g_sum[32];
__device__ static float g_sumsq[32];

// ---------------------------------------------------------------------------
// cp.async helpers (Ampere+; legal under compute_100)
// ---------------------------------------------------------------------------
__device__ __forceinline__ uint32_t smem_u32(const void* p) {
    uint32_t a;
    asm("{ .reg .u64 t; cvta.to.shared.u64 t, %1; cvt.u32.u64 %0, t; }"
        : "=r"(a) : "l"(p));
    return a;
}
__device__ __forceinline__ void cp_async16(uint32_t dst, const void* src, int src_sz) {
    asm volatile("cp.async.ca.shared.global [%0], [%1], 16, %2;"
                 :: "r"(dst), "l"(src), "r"(src_sz) : "memory");
}
#define CP_COMMIT() asm volatile("cp.async.commit_group;" ::: "memory")
#define CP_WAIT0()  asm volatile("cp.async.wait_group 0;" ::: "memory")
#define CP_WAIT1()  asm volatile("cp.async.wait_group 1;" ::: "memory")
#define CP_WAIT2()  asm volatile("cp.async.wait_group 2;" ::: "memory")
#define CP_WAIT3()  asm volatile("cp.async.wait_group 3;" ::: "memory")
#define CP_WAIT4()  asm volatile("cp.async.wait_group 4;" ::: "memory")

// ---------------------------------------------------------------------------
// K1: fused prep. Blocks [0, scatter_blocks): gap-fill scatter (out_idx is
// strictly increasing over its valid prefix; every nbr slot written exactly
// once). Blocks [scatter_blocks, +setup_blocks): feats->fp16 + lane-order W
// fragment table + zero sums.
// ---------------------------------------------------------------------------
__global__ void k_prep(const float* __restrict__ feats,
                       const float* __restrict__ W,
                       const int* __restrict__ out_idx,
                       const int* __restrict__ in_idx,
                       int N, int pb, int scatter_blocks, int setup_blocks) {
    const int tid = threadIdx.x;
    if ((int)blockIdx.x < scatter_blocks) {
        int k = blockIdx.x / pb;
        int p = (blockIdx.x % pb) * 256 + tid;
        if (p >= N) return;
        long long base = (long long)k * N;
        int o = out_idx[base + p];
        bool valid = (p == 0) || (o > out_idx[base + p - 1]);
        if (!valid) return;
        int* nb = g_nbr + base;
        nb[o] = in_idx[base + p];
        int o_next = N;
        if (p + 1 < N) {
            int t = out_idx[base + p + 1];
            if (t > o) o_next = t;
        }
        for (int j = o + 1; j < o_next; ++j) nb[j] = -1;
        if (p == 0)
            for (int j = 0; j < o; ++j) nb[j] = -1;
        return;
    }
    // ---- setup part ----
    int idx0 = ((int)blockIdx.x - scatter_blocks) * 256 + tid;
    int stride = setup_blocks * 256;
    int n_f = N * 32, n_w = KVOL * 512;
    for (int i = idx0; i < n_f; i += stride)
        g_fh[i] = __float2half_rn(feats[i]);
    for (int i = idx0; i < n_w; i += stride) {
        int koff = i >> 9, t = i & 511;
        int p = t >> 7, lane = (t >> 2) & 31, j = t & 3;
        int s = 2 * p + (j >> 1), r = j & 1;
        int nt = s >> 1, kstep = s & 1;
        int g = lane >> 2, q = lane & 3;
        int o = nt * 8 + g;
        int k0 = kstep * 16 + 2 * q + (r ? 8 : 0);
        __half2 hv = __halves2half2(
            __float2half_rn(W[koff * 1024 + k0 * 32 + o]),
            __float2half_rn(W[koff * 1024 + (k0 + 1) * 32 + o]));
        g_wfh[i] = *(uint32_t*)&hv;
    }
    if (idx0 < 32) { g_sum[idx0] = 0.f; g_sumsq[idx0] = 0.f; }
}

// ---------------------------------------------------------------------------
// K3: warp-private 5-stage pipelined fp16 mma gather-GEMM (dynamic smem).
// One CTA / 128-voxel tile, 8 warps; warp w owns rows [w*16, w*16+16).
// Tile's index block bulk-loaded to smem in the prolog. Per warp-k:
// 2 LDS idx + 2 cp.async + 8 LDS.32 A + 4 LDG.128 B (L1-hot) + 8 MMA.
// ZERO __syncthreads in the main loop; 4 stages of gather in flight.
// ---------------------------------------------------------------------------
__global__ __launch_bounds__(256, 2) void k_conv_mma(float* __restrict__ out, int N) {
    extern __shared__ __align__(16) char dsm[];
    int* idx_s = (int*)(dsm + IDX_OFF);
    const int tid  = threadIdx.x;
    const int w    = tid >> 5;
    const int lane = tid & 31;
    const int g    = lane >> 2;
    const int q    = lane & 3;
    const int grp  = lane & 3;           // 16B group within row
    const int rr0  = lane >> 2;          // gather rows rr0, rr0+8
    const int obase = blockIdx.x * TILE_M;
    const int v0g   = obase + w * 16;    // warp's global row base
    const bool r0ok = (v0g + rr0) < N;
    const bool r1ok = (v0g + rr0 + 8) < N;

    char* a_w = dsm + w * STAGES * A_STAGE_B;
    uint32_t adst[STAGES][2];
    #pragma unroll
    for (int b = 0; b < STAGES; ++b) {
        adst[b][0] = smem_u32(a_w + b * A_STAGE_B + rr0 * ROWB + grp * 16);
        adst[b][1] = smem_u32(a_w + b * A_STAGE_B + (rr0 + 8) * ROWB + grp * 16);
    }

    float c_[4][4];
    #pragma unroll
    for (int nt = 0; nt < 4; ++nt)
        c_[nt][0] = c_[nt][1] = c_[nt][2] = c_[nt][3] = 0.f;

    // ---- prolog: bulk-load the tile's index block (27 x 512B) to smem ----
    {
        uint32_t ib = smem_u32(idx_s);
        for (int j = tid; j < KVOL * 32; j += 256) {
            int k = j >> 5, c = j & 31;
            cp_async16(ib + j * 16, g_nbr + (long long)k * N + obase + c * 4, 16);
        }
        CP_COMMIT();
        CP_WAIT0();
        __syncthreads();
    }

    auto issue_stage = [&](int k, int b) {
        const int* ip = idx_s + k * TILE_M + w * 16;
        int s0 = r0ok ? ip[rr0] : -1;
        int s1 = r1ok ? ip[rr0 + 8] : -1;
        const __half* p0 = g_fh + (s0 >= 0 ? (long long)s0 * 32 + grp * 8 : 0);
        const __half* p1 = g_fh + (s1 >= 0 ? (long long)s1 * 32 + grp * 8 : 0);
        cp_async16(adst[b][0], p0, s0 >= 0 ? 16 : 0);
        cp_async16(adst[b][1], p1, s1 >= 0 ? 16 : 0);
        CP_COMMIT();
    };
    auto compute = [&](int k, int b) {
        const char* ap = a_w + b * A_STAGE_B;
        uint32_t A[2][4];
        #pragma unroll
        for (int ks = 0; ks < 2; ++ks) {
            int base = ks * 32 + q * 4;
            A[ks][0] = *(const uint32_t*)(ap + g * ROWB + base);
            A[ks][1] = *(const uint32_t*)(ap + (g + 8) * ROWB + base);
            A[ks][2] = *(const uint32_t*)(ap + g * ROWB + base + 16);
            A[ks][3] = *(const uint32_t*)(ap + (g + 8) * ROWB + base + 16);
        }
        const uint4* wf = (const uint4*)(g_wfh + k * 512);
        uint4 U[4];
        #pragma unroll
        for (int p = 0; p < 4; ++p) U[p] = wf[p * 32 + lane];
        #pragma unroll
        for (int nt = 0; nt < 4; ++nt) {
            #pragma unroll
            for (int ks = 0; ks < 2; ++ks) {
                int s = nt * 2 + ks, p = s >> 1;
                uint32_t b0 = (s & 1) ? U[p].z : U[p].x;
                uint32_t b1 = (s & 1) ? U[p].w : U[p].y;
                asm volatile(
                    "mma.sync.aligned.m16n8k16.row.col.f32.f16.f16.f32 "
                    "{%0,%1,%2,%3}, {%4,%5,%6,%7}, {%8,%9}, {%0,%1,%2,%3};"
                    : "+f"(c_[nt][0]), "+f"(c_[nt][1]),
                      "+f"(c_[nt][2]), "+f"(c_[nt][3])
                    : "r"(A[ks][0]), "r"(A[ks][1]), "r"(A[ks][2]), "r"(A[ks][3]),
                      "r"(b0), "r"(b1));
            }
        }
    };

    // prolog: stages 0..4 in flight
    #pragma unroll
    for (int b = 0; b < STAGES; ++b) issue_stage(b, b);

    int b = 0;
    #pragma unroll 1
    for (int k = 0; k < KVOL; ++k) {
        int wn = KVOL - 1 - k;
        if (wn >= 4) CP_WAIT4();
        else if (wn == 3) CP_WAIT3();
        else if (wn == 2) CP_WAIT2();
        else if (wn == 1) CP_WAIT1();
        else CP_WAIT0();
        __syncwarp();
        compute(k, b);
        if (k + STAGES < KVOL) issue_stage(k + STAGES, b);
        if (++b == STAGES) b = 0;
    }

    // ---- epilogue: store pre-BN rows -------------------------------------
    int r0g = v0g + g;
    int r1g = r0g + 8;
    #pragma unroll
    for (int nt = 0; nt < 4; ++nt) {
        if (r0g < N)
            *(float2*)(out + (long long)r0g * 32 + nt * 8 + 2 * q) =
                make_float2(c_[nt][0], c_[nt][1]);
        if (r1g < N)
            *(float2*)(out + (long long)r1g * 32 + nt * 8 + 2 * q) =
                make_float2(c_[nt][2], c_[nt][3]);
    }

    // ---- BN sums (padding rows are exactly zero, safe to include) --------
    float s[8], sq[8];
    #pragma unroll
    for (int nt = 0; nt < 4; ++nt) {
        s[nt * 2 + 0] = c_[nt][0] + c_[nt][2];
        s[nt * 2 + 1] = c_[nt][1] + c_[nt][3];
        sq[nt * 2 + 0] = c_[nt][0] * c_[nt][0] + c_[nt][2] * c_[nt][2];
        sq[nt * 2 + 1] = c_[nt][1] * c_[nt][1] + c_[nt][3] * c_[nt][3];
    }
    #pragma unroll
    for (int off = 16; off >= 4; off >>= 1) {
        #pragma unroll
        for (int e = 0; e < 8; ++e) {
            s[e]  += __shfl_xor_sync(~0u, s[e], off);
            sq[e] += __shfl_xor_sync(~0u, sq[e], off);
        }
    }
    __syncthreads();                 // all stage reads done; reuse dsm as s_red
    float* s_red = (float*)dsm;      // 512 floats
    if (lane < 4) {
        #pragma unroll
        for (int nt = 0; nt < 4; ++nt) {
            int ch = nt * 8 + 2 * lane;
            s_red[w * 32 + ch]           = s[nt * 2 + 0];
            s_red[w * 32 + ch + 1]       = s[nt * 2 + 1];
            s_red[256 + w * 32 + ch]     = sq[nt * 2 + 0];
            s_red[256 + w * 32 + ch + 1] = sq[nt * 2 + 1];
        }
    }
    __syncthreads();
    if (tid < 32) {
        float ts = 0.f, tq = 0.f;
        #pragma unroll
        for (int ww = 0; ww < 8; ++ww) {
            ts += s_red[ww * 32 + tid];
            tq += s_red[256 + ww * 32 + tid];
        }
        atomicAdd(&g_sum[tid], ts);
        atomicAdd(&g_sumsq[tid], tq);
    }
}

// ---------------------------------------------------------------------------
// K4: BN (batch stats, biased var) + ReLU, in place. Flat indexing, two
// independent float4s per thread (single pass, max MLP).
// ---------------------------------------------------------------------------
__global__ void k_bnrelu(const float* __restrict__ gamma,
                         const float* __restrict__ beta,
                         float* __restrict__ out, int N) {
    __shared__ float s_scale[32], s_shift[32];
    int tid = threadIdx.x;
    if (tid < 32) {
        float invN = 1.0f / (float)N;
        float mean = g_sum[tid] * invN;
        float var  = g_sumsq[tid] * invN - mean * mean;
        float sc   = gamma[tid] * rsqrtf(var + 1e-5f);
        s_scale[tid] = sc;
        s_shift[tid] = fmaf(-mean, sc, beta[tid]);
    }
    __syncthreads();
    long long total4 = (long long)N * 8;
    long long j0 = ((long long)blockIdx.x * 256 + tid) * 2;
    float4 v0, v1;
    bool ok0 = j0 < total4, ok1 = j0 + 1 < total4;
    if (ok0) v0 = *(const float4*)(out + j0 * 4);
    if (ok1) v1 = *(const float4*)(out + (j0 + 1) * 4);
    if (ok0) {
        int c = ((int)(j0 & 7)) * 4;
        float4 r;
        r.x = fmaxf(fmaf(v0.x, s_scale[c + 0], s_shift[c + 0]), 0.f);
        r.y = fmaxf(fmaf(v0.y, s_scale[c + 1], s_shift[c + 1]), 0.f);
        r.z = fmaxf(fmaf(v0.z, s_scale[c + 2], s_shift[c + 2]), 0.f);
        r.w = fmaxf(fmaf(v0.w, s_scale[c + 3], s_shift[c + 3]), 0.f);
        *(float4*)(out + j0 * 4) = r;
    }
    if (ok1) {
        int c = ((int)((j0 + 1) & 7)) * 4;
        float4 r;
        r.x = fmaxf(fmaf(v1.x, s_scale[c + 0], s_shift[c + 0]), 0.f);
        r.y = fmaxf(fmaf(v1.y, s_scale[c + 1], s_shift[c + 1]), 0.f);
        r.z = fmaxf(fmaf(v1.z, s_scale[c + 2], s_shift[c + 2]), 0.f);
        r.w = fmaxf(fmaf(v1.w, s_scale[c + 3], s_shift[c + 3]), 0.f);
        *(float4*)(out + (j0 + 1) * 4) = r;
    }
}

// ---------------------------------------------------------------------------
// Launch. Inputs: feats, W, gamma, beta, in_idx, out_idx, mask (mask unused)
// ---------------------------------------------------------------------------
extern "C" void kernel_launch(void* const* d_in, const int* in_sizes, int n_in,
                              void* d_out, int out_size) {
    const float* feats   = (const float*)d_in[0];
    const float* W       = (const float*)d_in[1];
    const float* gamma   = (const float*)d_in[2];
    const float* beta    = (const float*)d_in[3];
    const int*   in_idx  = (const int*)d_in[4];
    const int*   out_idx = (const int*)d_in[5];
    const int N = in_sizes[0] / 32;
    float* out = (float*)d_out;

    static bool attr_set = false;
    if (!attr_set) {
        cudaFuncSetAttribute(k_conv_mma,
                             cudaFuncAttributeMaxDynamicSharedMemorySize, DSMEM_B);
        attr_set = true;
    }

    int pb = (N + 255) / 256;
    int scatter_blocks = pb * KVOL;
    int setup_blocks = 1024;
    k_prep<<<scatter_blocks + setup_blocks, 256>>>(feats, W, out_idx, in_idx,
                                                   N, pb, scatter_blocks, setup_blocks);
    k_conv_mma<<<(N + TILE_M - 1) / TILE_M, 256, DSMEM_B>>>(out, N);
    int total4 = N * 8;
    k_bnrelu<<<(total4 + 511) / 512, 256>>>(gamma, beta, out, N);
}

// round 13
// speedup vs baseline: 1.0857x; 1.0857x over previous
#include <cuda_runtime.h>
#include <cuda_fp16.h>
#include <cstdint>

#define KVOL 27
#define MAXN 131072
#define TILE_M 128
#define ROWB 80     // smem bytes per 32-half row (64B data + 16B pad)
#define STAGES 5
#define A_STAGE_B (16 * ROWB)                    // 1280 B per warp-stage
#define A_REGION  (8 * STAGES * A_STAGE_B)       // 51200 B
#define IDX_OFF   A_REGION                       // idx block after A region
#define DSMEM_B   (A_REGION + KVOL * TILE_M * 4) // 65024 B

// ---------------------------------------------------------------------------
// Scratch (device globals — allocation rules forbid cudaMalloc)
// ---------------------------------------------------------------------------
__device__ static int      g_nbr[KVOL * MAXN];               // nbr[k][o] = in idx or -1
__device__ __align__(16) static __half   g_fh[MAXN * 32];    // feats, fp16
__device__ __align__(16) static uint32_t g_wfh[KVOL * 512];  // lane-order fp16 B frags
__device__ static float g_sum[32];
__device__ static float g_sumsq[32];

// ---------------------------------------------------------------------------
// cp.async helpers (Ampere+; legal under compute_100)
// ---------------------------------------------------------------------------
__device__ __forceinline__ uint32_t smem_u32(const void* p) {
    uint32_t a;
    asm("{ .reg .u64 t; cvta.to.shared.u64 t, %1; cvt.u32.u64 %0, t; }"
        : "=r"(a) : "l"(p));
    return a;
}
__device__ __forceinline__ void cp_async16(uint32_t dst, const void* src, int src_sz) {
    asm volatile("cp.async.ca.shared.global [%0], [%1], 16, %2;"
                 :: "r"(dst), "l"(src), "r"(src_sz) : "memory");
}
#define CP_COMMIT() asm volatile("cp.async.commit_group;" ::: "memory")
template <int n>
__device__ __forceinline__ void cp_wait() {
    asm volatile("cp.async.wait_group %0;" :: "n"(n) : "memory");
}

// ---------------------------------------------------------------------------
// K1: fused prep. Blocks [0, scatter_blocks): gap-fill scatter (out_idx is
// strictly increasing over its valid prefix; every nbr slot written exactly
// once). Blocks [scatter_blocks, +setup_blocks): feats->fp16 + lane-order W
// fragment table + zero sums.
// ---------------------------------------------------------------------------
__global__ void k_prep(const float* __restrict__ feats,
                       const float* __restrict__ W,
                       const int* __restrict__ out_idx,
                       const int* __restrict__ in_idx,
                       int N, int pb, int scatter_blocks, int setup_blocks) {
    const int tid = threadIdx.x;
    if ((int)blockIdx.x < scatter_blocks) {
        int k = blockIdx.x / pb;
        int p = (blockIdx.x % pb) * 256 + tid;
        if (p >= N) return;
        long long base = (long long)k * N;
        int o = out_idx[base + p];
        bool valid = (p == 0) || (o > out_idx[base + p - 1]);
        if (!valid) return;
        int* nb = g_nbr + base;
        nb[o] = in_idx[base + p];
        int o_next = N;
        if (p + 1 < N) {
            int t = out_idx[base + p + 1];
            if (t > o) o_next = t;
        }
        for (int j = o + 1; j < o_next; ++j) nb[j] = -1;
        if (p == 0)
            for (int j = 0; j < o; ++j) nb[j] = -1;
        return;
    }
    // ---- setup part ----
    int idx0 = ((int)blockIdx.x - scatter_blocks) * 256 + tid;
    int stride = setup_blocks * 256;
    int n_f = N * 32, n_w = KVOL * 512;
    for (int i = idx0; i < n_f; i += stride)
        g_fh[i] = __float2half_rn(feats[i]);
    for (int i = idx0; i < n_w; i += stride) {
        int koff = i >> 9, t = i & 511;
        int p = t >> 7, lane = (t >> 2) & 31, j = t & 3;
        int s = 2 * p + (j >> 1), r = j & 1;
        int nt = s >> 1, kstep = s & 1;
        int g = lane >> 2, q = lane & 3;
        int o = nt * 8 + g;
        int k0 = kstep * 16 + 2 * q + (r ? 8 : 0);
        __half2 hv = __halves2half2(
            __float2half_rn(W[koff * 1024 + k0 * 32 + o]),
            __float2half_rn(W[koff * 1024 + (k0 + 1) * 32 + o]));
        g_wfh[i] = *(uint32_t*)&hv;
    }
    if (idx0 < 32) { g_sum[idx0] = 0.f; g_sumsq[idx0] = 0.f; }
}

// ---------------------------------------------------------------------------
// K3: warp-private 5-stage pipelined fp16 mma gather-GEMM (dynamic smem).
// FULLY UNROLLED main loop: every k / buffer index / wait-group count is a
// compile-time constant (no dynamically-indexed local arrays -> no LDL/STL).
// Per warp-k: 2 LDS idx + 2 cp.async + 8 LDS.32 A + 4 LDG.128 B + 8 MMA.
// ZERO __syncthreads in the main loop; 4 gather stages in flight.
// ---------------------------------------------------------------------------
__global__ __launch_bounds__(256, 2) void k_conv_mma(float* __restrict__ out, int N) {
    extern __shared__ __align__(16) char dsm[];
    int* idx_s = (int*)(dsm + IDX_OFF);
    const int tid  = threadIdx.x;
    const int w    = tid >> 5;
    const int lane = tid & 31;
    const int g    = lane >> 2;
    const int q    = lane & 3;
    const int grp  = lane & 3;           // 16B group within row
    const int rr0  = lane >> 2;          // gather rows rr0, rr0+8
    const int obase = blockIdx.x * TILE_M;
    const int v0g   = obase + w * 16;    // warp's global row base
    const bool r0ok = (v0g + rr0) < N;
    const bool r1ok = (v0g + rr0 + 8) < N;

    char* a_w = dsm + w * STAGES * A_STAGE_B;
    uint32_t adst[STAGES][2];
    #pragma unroll
    for (int b = 0; b < STAGES; ++b) {
        adst[b][0] = smem_u32(a_w + b * A_STAGE_B + rr0 * ROWB + grp * 16);
        adst[b][1] = smem_u32(a_w + b * A_STAGE_B + (rr0 + 8) * ROWB + grp * 16);
    }

    float c_[4][4];
    #pragma unroll
    for (int nt = 0; nt < 4; ++nt)
        c_[nt][0] = c_[nt][1] = c_[nt][2] = c_[nt][3] = 0.f;

    // ---- prolog: bulk-load the tile's index block (27 x 512B) to smem ----
    {
        uint32_t ib = smem_u32(idx_s);
        for (int j = tid; j < KVOL * 32; j += 256) {
            int k = j >> 5, c = j & 31;
            cp_async16(ib + j * 16, g_nbr + (long long)k * N + obase + c * 4, 16);
        }
        CP_COMMIT();
        cp_wait<0>();
        __syncthreads();
    }

    auto issue_stage = [&](int k, int b) {
        const int* ip = idx_s + k * TILE_M + w * 16;
        int s0 = r0ok ? ip[rr0] : -1;
        int s1 = r1ok ? ip[rr0 + 8] : -1;
        const __half* p0 = g_fh + (s0 >= 0 ? (long long)s0 * 32 + grp * 8 : 0);
        const __half* p1 = g_fh + (s1 >= 0 ? (long long)s1 * 32 + grp * 8 : 0);
        cp_async16(adst[b][0], p0, s0 >= 0 ? 16 : 0);
        cp_async16(adst[b][1], p1, s1 >= 0 ? 16 : 0);
        CP_COMMIT();
    };
    auto compute = [&](int k, int b) {
        const char* ap = a_w + b * A_STAGE_B;
        uint32_t A[2][4];
        #pragma unroll
        for (int ks = 0; ks < 2; ++ks) {
            int base = ks * 32 + q * 4;
            A[ks][0] = *(const uint32_t*)(ap + g * ROWB + base);
            A[ks][1] = *(const uint32_t*)(ap + (g + 8) * ROWB + base);
            A[ks][2] = *(const uint32_t*)(ap + g * ROWB + base + 16);
            A[ks][3] = *(const uint32_t*)(ap + (g + 8) * ROWB + base + 16);
        }
        const uint4* wf = (const uint4*)(g_wfh + k * 512);
        uint4 U[4];
        #pragma unroll
        for (int p = 0; p < 4; ++p) U[p] = wf[p * 32 + lane];
        #pragma unroll
        for (int nt = 0; nt < 4; ++nt) {
            #pragma unroll
            for (int ks = 0; ks < 2; ++ks) {
                int s = nt * 2 + ks, p = s >> 1;
                uint32_t b0 = (s & 1) ? U[p].z : U[p].x;
                uint32_t b1 = (s & 1) ? U[p].w : U[p].y;
                asm volatile(
                    "mma.sync.aligned.m16n8k16.row.col.f32.f16.f16.f32 "
                    "{%0,%1,%2,%3}, {%4,%5,%6,%7}, {%8,%9}, {%0,%1,%2,%3};"
                    : "+f"(c_[nt][0]), "+f"(c_[nt][1]),
                      "+f"(c_[nt][2]), "+f"(c_[nt][3])
                    : "r"(A[ks][0]), "r"(A[ks][1]), "r"(A[ks][2]), "r"(A[ks][3]),
                      "r"(b0), "r"(b1));
            }
        }
    };

    // prolog: stages 0..4 in flight
    #pragma unroll
    for (int b = 0; b < STAGES; ++b) issue_stage(b, b);

    // fully unrolled main loop: k, b, and wait count are compile-time
    #pragma unroll
    for (int k = 0; k < KVOL; ++k) {
        const int b = k % STAGES;
        const int wn = KVOL - 1 - k;
        if (wn >= 4) cp_wait<4>();
        else if (wn == 3) cp_wait<3>();
        else if (wn == 2) cp_wait<2>();
        else if (wn == 1) cp_wait<1>();
        else cp_wait<0>();
        __syncwarp();
        compute(k, b);
        if (k + STAGES < KVOL) issue_stage(k + STAGES, b);
    }

    // ---- epilogue: store pre-BN rows -------------------------------------
    int r0g = v0g + g;
    int r1g = r0g + 8;
    #pragma unroll
    for (int nt = 0; nt < 4; ++nt) {
        if (r0g < N)
            *(float2*)(out + (long long)r0g * 32 + nt * 8 + 2 * q) =
                make_float2(c_[nt][0], c_[nt][1]);
        if (r1g < N)
            *(float2*)(out + (long long)r1g * 32 + nt * 8 + 2 * q) =
                make_float2(c_[nt][2], c_[nt][3]);
    }

    // ---- BN sums (padding rows are exactly zero, safe to include) --------
    float s[8], sq[8];
    #pragma unroll
    for (int nt = 0; nt < 4; ++nt) {
        s[nt * 2 + 0] = c_[nt][0] + c_[nt][2];
        s[nt * 2 + 1] = c_[nt][1] + c_[nt][3];
        sq[nt * 2 + 0] = c_[nt][0] * c_[nt][0] + c_[nt][2] * c_[nt][2];
        sq[nt * 2 + 1] = c_[nt][1] * c_[nt][1] + c_[nt][3] * c_[nt][3];
    }
    #pragma unroll
    for (int off = 16; off >= 4; off >>= 1) {
        #pragma unroll
        for (int e = 0; e < 8; ++e) {
            s[e]  += __shfl_xor_sync(~0u, s[e], off);
            sq[e] += __shfl_xor_sync(~0u, sq[e], off);
        }
    }
    __syncthreads();                 // all stage reads done; reuse dsm as s_red
    float* s_red = (float*)dsm;      // 512 floats
    if (lane < 4) {
        #pragma unroll
        for (int nt = 0; nt < 4; ++nt) {
            int ch = nt * 8 + 2 * lane;
            s_red[w * 32 + ch]           = s[nt * 2 + 0];
            s_red[w * 32 + ch + 1]       = s[nt * 2 + 1];
            s_red[256 + w * 32 + ch]     = sq[nt * 2 + 0];
            s_red[256 + w * 32 + ch + 1] = sq[nt * 2 + 1];
        }
    }
    __syncthreads();
    if (tid < 32) {
        float ts = 0.f, tq = 0.f;
        #pragma unroll
        for (int ww = 0; ww < 8; ++ww) {
            ts += s_red[ww * 32 + tid];
            tq += s_red[256 + ww * 32 + tid];
        }
        atomicAdd(&g_sum[tid], ts);
        atomicAdd(&g_sumsq[tid], tq);
    }
}

// ---------------------------------------------------------------------------
// K4: BN (batch stats, biased var) + ReLU, in place. Flat indexing, two
// independent float4s per thread (single pass, max MLP).
// ---------------------------------------------------------------------------
__global__ void k_bnrelu(const float* __restrict__ gamma,
                         const float* __restrict__ beta,
                         float* __restrict__ out, int N) {
    __shared__ float s_scale[32], s_shift[32];
    int tid = threadIdx.x;
    if (tid < 32) {
        float invN = 1.0f / (float)N;
        float mean = g_sum[tid] * invN;
        float var  = g_sumsq[tid] * invN - mean * mean;
        float sc   = gamma[tid] * rsqrtf(var + 1e-5f);
        s_scale[tid] = sc;
        s_shift[tid] = fmaf(-mean, sc, beta[tid]);
    }
    __syncthreads();
    long long total4 = (long long)N * 8;
    long long j0 = ((long long)blockIdx.x * 256 + tid) * 2;
    float4 v0, v1;
    bool ok0 = j0 < total4, ok1 = j0 + 1 < total4;
    if (ok0) v0 = *(const float4*)(out + j0 * 4);
    if (ok1) v1 = *(const float4*)(out + (j0 + 1) * 4);
    if (ok0) {
        int c = ((int)(j0 & 7)) * 4;
        float4 r;
        r.x = fmaxf(fmaf(v0.x, s_scale[c + 0], s_shift[c + 0]), 0.f);
        r.y = fmaxf(fmaf(v0.y, s_scale[c + 1], s_shift[c + 1]), 0.f);
        r.z = fmaxf(fmaf(v0.z, s_scale[c + 2], s_shift[c + 2]), 0.f);
        r.w = fmaxf(fmaf(v0.w, s_scale[c + 3], s_shift[c + 3]), 0.f);
        *(float4*)(out + j0 * 4) = r;
    }
    if (ok1) {
        int c = ((int)((j0 + 1) & 7)) * 4;
        float4 r;
        r.x = fmaxf(fmaf(v1.x, s_scale[c + 0], s_shift[c + 0]), 0.f);
        r.y = fmaxf(fmaf(v1.y, s_scale[c + 1], s_shift[c + 1]), 0.f);
        r.z = fmaxf(fmaf(v1.z, s_scale[c + 2], s_shift[c + 2]), 0.f);
        r.w = fmaxf(fmaf(v1.w, s_scale[c + 3], s_shift[c + 3]), 0.f);
        *(float4*)(out + (j0 + 1) * 4) = r;
    }
}

// ---------------------------------------------------------------------------
// Launch. Inputs: feats, W, gamma, beta, in_idx, out_idx, mask (mask unused)
// ---------------------------------------------------------------------------
extern "C" void kernel_launch(void* const* d_in, const int* in_sizes, int n_in,
                              void* d_out, int out_size) {
    const float* feats   = (const float*)d_in[0];
    const float* W       = (const float*)d_in[1];
    const float* gamma   = (const float*)d_in[2];
    const float* beta    = (const float*)d_in[3];
    const int*   in_idx  = (const int*)d_in[4];
    const int*   out_idx = (const int*)d_in[5];
    const int N = in_sizes[0] / 32;
    float* out = (float*)d_out;

    static bool attr_set = false;
    if (!attr_set) {
        cudaFuncSetAttribute(k_conv_mma,
                             cudaFuncAttributeMaxDynamicSharedMemorySize, DSMEM_B);
        attr_set = true;
    }

    int pb = (N + 255) / 256;
    int scatter_blocks = pb * KVOL;
    int setup_blocks = 1024;
    k_prep<<<scatter_blocks + setup_blocks, 256>>>(feats, W, out_idx, in_idx,
                                                   N, pb, scatter_blocks, setup_blocks);
    k_conv_mma<<<(N + TILE_M - 1) / TILE_M, 256, DSMEM_B>>>(out, N);
    int total4 = N * 8;
    k_bnrelu<<<(total4 + 511) / 512, 256>>>(gamma, beta, out, N);
}

// round 14
// speedup vs baseline: 1.1125x; 1.0247x over previous
#include <cuda_runtime.h>
#include <cuda_fp16.h>
#include <cstdint>

#define KVOL 27
#define MAXN 131072
#define TILE_M 128
#define ROWB 80     // smem bytes per 32-half row (64B data + 16B pad)
#define STAGES 3
#define A_STAGE_B (16 * ROWB)                    // 1280 B per warp-stage
#define A_REGION  (8 * STAGES * A_STAGE_B)       // 30720 B
#define IDX_OFF   A_REGION                       // idx block after A region
#define DSMEM_B   (A_REGION + KVOL * TILE_M * 4) // 44544 B

// ---------------------------------------------------------------------------
// Scratch (device globals — allocation rules forbid cudaMalloc)
// ---------------------------------------------------------------------------
__device__ static int      g_nbr[KVOL * MAXN];               // nbr[k][o] = in idx or -1
__device__ __align__(16) static __half   g_fh[MAXN * 32];    // feats, fp16
__device__ __align__(16) static uint32_t g_wfh[KVOL * 512];  // lane-order fp16 B frags
__device__ static float g_sum[32];
__device__ static float g_sumsq[32];

// ---------------------------------------------------------------------------
// cp.async helpers (Ampere+; legal under compute_100)
// ---------------------------------------------------------------------------
__device__ __forceinline__ uint32_t smem_u32(const void* p) {
    uint32_t a;
    asm("{ .reg .u64 t; cvta.to.shared.u64 t, %1; cvt.u32.u64 %0, t; }"
        : "=r"(a) : "l"(p));
    return a;
}
__device__ __forceinline__ void cp_async16(uint32_t dst, const void* src, int src_sz) {
    asm volatile("cp.async.ca.shared.global [%0], [%1], 16, %2;"
                 :: "r"(dst), "l"(src), "r"(src_sz) : "memory");
}
#define CP_COMMIT() asm volatile("cp.async.commit_group;" ::: "memory")
template <int n>
__device__ __forceinline__ void cp_wait() {
    asm volatile("cp.async.wait_group %0;" :: "n"(n) : "memory");
}

// ---------------------------------------------------------------------------
// K1: fused prep. Blocks [0, scatter_blocks): gap-fill scatter (out_idx is
// strictly increasing over its valid prefix; every nbr slot written exactly
// once). Blocks [scatter_blocks, +setup_blocks): feats->fp16 (vectorized,
// float4 -> 2x half2) + lane-order W fragment table + zero sums.
// ---------------------------------------------------------------------------
__global__ void k_prep(const float* __restrict__ feats,
                       const float* __restrict__ W,
                       const int* __restrict__ out_idx,
                       const int* __restrict__ in_idx,
                       int N, int pb, int scatter_blocks, int setup_blocks) {
    const int tid = threadIdx.x;
    if ((int)blockIdx.x < scatter_blocks) {
        int k = blockIdx.x / pb;
        int p = (blockIdx.x % pb) * 256 + tid;
        if (p >= N) return;
        long long base = (long long)k * N;
        int o = out_idx[base + p];
        bool valid = (p == 0) || (o > out_idx[base + p - 1]);
        if (!valid) return;
        int* nb = g_nbr + base;
        nb[o] = in_idx[base + p];
        int o_next = N;
        if (p + 1 < N) {
            int t = out_idx[base + p + 1];
            if (t > o) o_next = t;
        }
        for (int j = o + 1; j < o_next; ++j) nb[j] = -1;
        if (p == 0)
            for (int j = 0; j < o; ++j) nb[j] = -1;
        return;
    }
    // ---- setup part ----
    int idx0 = ((int)blockIdx.x - scatter_blocks) * 256 + tid;
    int stride = setup_blocks * 256;
    int n_f4 = N * 8;                      // float4 count
    const float4* f4 = (const float4*)feats;
    uint2* fh2 = (uint2*)g_fh;             // 4 halves per uint2
    for (int i = idx0; i < n_f4; i += stride) {
        float4 v = f4[i];
        __half2 h0 = __floats2half2_rn(v.x, v.y);
        __half2 h1 = __floats2half2_rn(v.z, v.w);
        uint2 u;
        u.x = *(uint32_t*)&h0;
        u.y = *(uint32_t*)&h1;
        fh2[i] = u;
    }
    int n_w = KVOL * 512;
    for (int i = idx0; i < n_w; i += stride) {
        int koff = i >> 9, t = i & 511;
        int p = t >> 7, lane = (t >> 2) & 31, j = t & 3;
        int s = 2 * p + (j >> 1), r = j & 1;
        int nt = s >> 1, kstep = s & 1;
        int g = lane >> 2, q = lane & 3;
        int o = nt * 8 + g;
        int k0 = kstep * 16 + 2 * q + (r ? 8 : 0);
        __half2 hv = __halves2half2(
            __float2half_rn(W[koff * 1024 + k0 * 32 + o]),
            __float2half_rn(W[koff * 1024 + (k0 + 1) * 32 + o]));
        g_wfh[i] = *(uint32_t*)&hv;
    }
    if (idx0 < 32) { g_sum[idx0] = 0.f; g_sumsq[idx0] = 0.f; }
}

// ---------------------------------------------------------------------------
// K3: warp-private 3-stage pipelined fp16 mma gather-GEMM (dynamic smem),
// targeted at 3 CTAs/SM (24 warps) via launch_bounds(256,3). Fully unrolled
// main loop (compile-time buffer indices). B fragments loaded one uint4 per
// nt (slot p == nt) to minimize live registers. ZERO __syncthreads in loop.
// ---------------------------------------------------------------------------
__global__ __launch_bounds__(256, 3) void k_conv_mma(float* __restrict__ out, int N) {
    extern __shared__ __align__(16) char dsm[];
    int* idx_s = (int*)(dsm + IDX_OFF);
    const int tid  = threadIdx.x;
    const int w    = tid >> 5;
    const int lane = tid & 31;
    const int g    = lane >> 2;
    const int q    = lane & 3;
    const int grp  = lane & 3;           // 16B group within row
    const int rr0  = lane >> 2;          // gather rows rr0, rr0+8
    const int obase = blockIdx.x * TILE_M;
    const int v0g   = obase + w * 16;    // warp's global row base
    const bool r0ok = (v0g + rr0) < N;
    const bool r1ok = (v0g + rr0 + 8) < N;

    char* a_w = dsm + w * STAGES * A_STAGE_B;
    uint32_t adst[STAGES][2];
    #pragma unroll
    for (int b = 0; b < STAGES; ++b) {
        adst[b][0] = smem_u32(a_w + b * A_STAGE_B + rr0 * ROWB + grp * 16);
        adst[b][1] = smem_u32(a_w + b * A_STAGE_B + (rr0 + 8) * ROWB + grp * 16);
    }

    float c_[4][4];
    #pragma unroll
    for (int nt = 0; nt < 4; ++nt)
        c_[nt][0] = c_[nt][1] = c_[nt][2] = c_[nt][3] = 0.f;

    // ---- prolog: bulk-load the tile's index block (27 x 512B) to smem ----
    {
        uint32_t ib = smem_u32(idx_s);
        for (int j = tid; j < KVOL * 32; j += 256) {
            int k = j >> 5, c = j & 31;
            cp_async16(ib + j * 16, g_nbr + (long long)k * N + obase + c * 4, 16);
        }
        CP_COMMIT();
        cp_wait<0>();
        __syncthreads();
    }

    auto issue_stage = [&](int k, int b) {
        const int* ip = idx_s + k * TILE_M + w * 16;
        int s0 = r0ok ? ip[rr0] : -1;
        int s1 = r1ok ? ip[rr0 + 8] : -1;
        const __half* p0 = g_fh + (s0 >= 0 ? (long long)s0 * 32 + grp * 8 : 0);
        const __half* p1 = g_fh + (s1 >= 0 ? (long long)s1 * 32 + grp * 8 : 0);
        cp_async16(adst[b][0], p0, s0 >= 0 ? 16 : 0);
        cp_async16(adst[b][1], p1, s1 >= 0 ? 16 : 0);
        CP_COMMIT();
    };
    auto compute = [&](int k, int b) {
        const char* ap = a_w + b * A_STAGE_B;
        uint32_t A[2][4];
        #pragma unroll
        for (int ks = 0; ks < 2; ++ks) {
            int base = ks * 32 + q * 4;
            A[ks][0] = *(const uint32_t*)(ap + g * ROWB + base);
            A[ks][1] = *(const uint32_t*)(ap + (g + 8) * ROWB + base);
            A[ks][2] = *(const uint32_t*)(ap + g * ROWB + base + 16);
            A[ks][3] = *(const uint32_t*)(ap + (g + 8) * ROWB + base + 16);
        }
        const uint4* wf = (const uint4*)(g_wfh + k * 512);
        #pragma unroll
        for (int nt = 0; nt < 4; ++nt) {
            uint4 u = wf[nt * 32 + lane];   // slot p == nt: one uint4 per nt
            asm volatile(
                "mma.sync.aligned.m16n8k16.row.col.f32.f16.f16.f32 "
                "{%0,%1,%2,%3}, {%4,%5,%6,%7}, {%8,%9}, {%0,%1,%2,%3};"
                : "+f"(c_[nt][0]), "+f"(c_[nt][1]),
                  "+f"(c_[nt][2]), "+f"(c_[nt][3])
                : "r"(A[0][0]), "r"(A[0][1]), "r"(A[0][2]), "r"(A[0][3]),
                  "r"(u.x), "r"(u.y));
            asm volatile(
                "mma.sync.aligned.m16n8k16.row.col.f32.f16.f16.f32 "
                "{%0,%1,%2,%3}, {%4,%5,%6,%7}, {%8,%9}, {%0,%1,%2,%3};"
                : "+f"(c_[nt][0]), "+f"(c_[nt][1]),
                  "+f"(c_[nt][2]), "+f"(c_[nt][3])
                : "r"(A[1][0]), "r"(A[1][1]), "r"(A[1][2]), "r"(A[1][3]),
                  "r"(u.z), "r"(u.w));
        }
    };

    // prolog: stages 0..2 in flight
    #pragma unroll
    for (int b = 0; b < STAGES; ++b) issue_stage(b, b);

    // fully unrolled main loop: k, b, and wait count are compile-time
    #pragma unroll
    for (int k = 0; k < KVOL; ++k) {
        const int b = k % STAGES;
        const int wn = KVOL - 1 - k;
        if (wn >= 2) cp_wait<2>();
        else if (wn == 1) cp_wait<1>();
        else cp_wait<0>();
        __syncwarp();
        compute(k, b);
        if (k + STAGES < KVOL) issue_stage(k + STAGES, b);
    }

    // ---- epilogue: store pre-BN rows -------------------------------------
    int r0g = v0g + g;
    int r1g = r0g + 8;
    #pragma unroll
    for (int nt = 0; nt < 4; ++nt) {
        if (r0g < N)
            *(float2*)(out + (long long)r0g * 32 + nt * 8 + 2 * q) =
                make_float2(c_[nt][0], c_[nt][1]);
        if (r1g < N)
            *(float2*)(out + (long long)r1g * 32 + nt * 8 + 2 * q) =
                make_float2(c_[nt][2], c_[nt][3]);
    }

    // ---- BN sums (padding rows are exactly zero, safe to include) --------
    float s[8], sq[8];
    #pragma unroll
    for (int nt = 0; nt < 4; ++nt) {
        s[nt * 2 + 0] = c_[nt][0] + c_[nt][2];
        s[nt * 2 + 1] = c_[nt][1] + c_[nt][3];
        sq[nt * 2 + 0] = c_[nt][0] * c_[nt][0] + c_[nt][2] * c_[nt][2];
        sq[nt * 2 + 1] = c_[nt][1] * c_[nt][1] + c_[nt][3] * c_[nt][3];
    }
    #pragma unroll
    for (int off = 16; off >= 4; off >>= 1) {
        #pragma unroll
        for (int e = 0; e < 8; ++e) {
            s[e]  += __shfl_xor_sync(~0u, s[e], off);
            sq[e] += __shfl_xor_sync(~0u, sq[e], off);
        }
    }
    __syncthreads();                 // all stage reads done; reuse dsm as s_red
    float* s_red = (float*)dsm;      // 512 floats
    if (lane < 4) {
        #pragma unroll
        for (int nt = 0; nt < 4; ++nt) {
            int ch = nt * 8 + 2 * lane;
            s_red[w * 32 + ch]           = s[nt * 2 + 0];
            s_red[w * 32 + ch + 1]       = s[nt * 2 + 1];
            s_red[256 + w * 32 + ch]     = sq[nt * 2 + 0];
            s_red[256 + w * 32 + ch + 1] = sq[nt * 2 + 1];
        }
    }
    __syncthreads();
    if (tid < 32) {
        float ts = 0.f, tq = 0.f;
        #pragma unroll
        for (int ww = 0; ww < 8; ++ww) {
            ts += s_red[ww * 32 + tid];
            tq += s_red[256 + ww * 32 + tid];
        }
        atomicAdd(&g_sum[tid], ts);
        atomicAdd(&g_sumsq[tid], tq);
    }
}

// ---------------------------------------------------------------------------
// K4: BN (batch stats, biased var) + ReLU, in place. Flat indexing, two
// independent float4s per thread (single pass, max MLP).
// ---------------------------------------------------------------------------
__global__ void k_bnrelu(const float* __restrict__ gamma,
                         const float* __restrict__ beta,
                         float* __restrict__ out, int N) {
    __shared__ float s_scale[32], s_shift[32];
    int tid = threadIdx.x;
    if (tid < 32) {
        float invN = 1.0f / (float)N;
        float mean = g_sum[tid] * invN;
        float var  = g_sumsq[tid] * invN - mean * mean;
        float sc   = gamma[tid] * rsqrtf(var + 1e-5f);
        s_scale[tid] = sc;
        s_shift[tid] = fmaf(-mean, sc, beta[tid]);
    }
    __syncthreads();
    long long total4 = (long long)N * 8;
    long long j0 = ((long long)blockIdx.x * 256 + tid) * 2;
    float4 v0, v1;
    bool ok0 = j0 < total4, ok1 = j0 + 1 < total4;
    if (ok0) v0 = *(const float4*)(out + j0 * 4);
    if (ok1) v1 = *(const float4*)(out + (j0 + 1) * 4);
    if (ok0) {
        int c = ((int)(j0 & 7)) * 4;
        float4 r;
        r.x = fmaxf(fmaf(v0.x, s_scale[c + 0], s_shift[c + 0]), 0.f);
        r.y = fmaxf(fmaf(v0.y, s_scale[c + 1], s_shift[c + 1]), 0.f);
        r.z = fmaxf(fmaf(v0.z, s_scale[c + 2], s_shift[c + 2]), 0.f);
        r.w = fmaxf(fmaf(v0.w, s_scale[c + 3], s_shift[c + 3]), 0.f);
        *(float4*)(out + j0 * 4) = r;
    }
    if (ok1) {
        int c = ((int)((j0 + 1) & 7)) * 4;
        float4 r;
        r.x = fmaxf(fmaf(v1.x, s_scale[c + 0], s_shift[c + 0]), 0.f);
        r.y = fmaxf(fmaf(v1.y, s_scale[c + 1], s_shift[c + 1]), 0.f);
        r.z = fmaxf(fmaf(v1.z, s_scale[c + 2], s_shift[c + 2]), 0.f);
        r.w = fmaxf(fmaf(v1.w, s_scale[c + 3], s_shift[c + 3]), 0.f);
        *(float4*)(out + (j0 + 1) * 4) = r;
    }
}

// ---------------------------------------------------------------------------
// Launch. Inputs: feats, W, gamma, beta, in_idx, out_idx, mask (mask unused)
// ---------------------------------------------------------------------------
extern "C" void kernel_launch(void* const* d_in, const int* in_sizes, int n_in,
                              void* d_out, int out_size) {
    const float* feats   = (const float*)d_in[0];
    const float* W       = (const float*)d_in[1];
    const float* gamma   = (const float*)d_in[2];
    const float* beta    = (const float*)d_in[3];
    const int*   in_idx  = (const int*)d_in[4];
    const int*   out_idx = (const int*)d_in[5];
    const int N = in_sizes[0] / 32;
    float* out = (float*)d_out;

    static bool attr_set = false;
    if (!attr_set) {
        cudaFuncSetAttribute(k_conv_mma,
                             cudaFuncAttributeMaxDynamicSharedMemorySize, DSMEM_B);
        attr_set = true;
    }

    int pb = (N + 255) / 256;
    int scatter_blocks = pb * KVOL;
    int setup_blocks = 1024;
    k_prep<<<scatter_blocks + setup_blocks, 256>>>(feats, W, out_idx, in_idx,
                                                   N, pb, scatter_blocks, setup_blocks);
    k_conv_mma<<<(N + TILE_M - 1) / TILE_M, 256, DSMEM_B>>>(out, N);
    int total4 = N * 8;
    k_bnrelu<<<(total4 + 511) / 512, 256>>>(gamma, beta, out, N);
}